// round 13
// baseline (speedup 1.0000x reference)
#include <cuda_runtime.h>
#include <cuda_fp16.h>
#include <math.h>
#include <float.h>
#include <stdint.h>

// Problem constants
#define BB 16
#define NN 1000
#define EE 4000
#define DD 256
#define NH 4
#define HD 1024
#define LL 64
#define ACT 128
#define OO 256
#define G3 768
#define QKVS_W 4096

// ================= scratch (device globals) =================
__device__ __align__(16) __half g_x[BB*NN*DD];
__device__ __align__(16) __half g_ea[BB*EE*DD];
__device__ __align__(16) __half g_qkvs[(size_t)BB*NN*QKVS_W];  // q|k|v|skip fp16
__device__ __align__(16) __half g_e[(size_t)BB*EE*HD];
__device__ __align__(16) __half g_h[(size_t)BB*NN*HD];
__device__ __align__(16) __half g_gr[BB*NN*DD];                // fp16 graph_repr
__device__ int   g_cnt[BB*NN];
__device__ int   g_off[BB*NN];
__device__ int   g_cur[BB*NN];
__device__ int   g_eord[BB*EE];
__device__ __align__(16) __half g_inve[BB*LL*DD];
__device__ __align__(16) __half g_invh[BB*LL*DD];
__device__ __align__(16) float g_gx[BB*LL*G3];
__device__ __align__(16) __half g_Wh8[DD*G3];   // W_hh fp16 packed (j8, g, 8)
__device__ float g_invvec[BB*OO];
__device__ float g_biasN[QKVS_W];
// fp16 weight buffers, [N,K] layout (k contiguous)
__device__ __align__(16) __half g_bN[QKVS_W*DD];
__device__ __align__(16) __half g_bE[HD*DD];
__device__ __align__(16) __half g_bw1[DD*HD];
__device__ __align__(16) __half g_bwp[DD*DD];
__device__ __align__(16) __half g_bih[G3*DD];

// ================= helpers =================
__device__ __forceinline__ uint32_t smem_to_u32(const void* smem_ptr) {
    uint32_t addr;
    asm("{ .reg .u64 tmp; cvta.to.shared.u64 tmp, %1; cvt.u32.u64 %0, tmp; }"
        : "=r"(addr) : "l"(smem_ptr));
    return addr;
}
__device__ __forceinline__ void ldsm4(uint32_t r[4], uint32_t addr) {
    asm volatile("ldmatrix.sync.aligned.m8n8.x4.shared.b16 {%0,%1,%2,%3}, [%4];"
        : "=r"(r[0]), "=r"(r[1]), "=r"(r[2]), "=r"(r[3]) : "r"(addr));
}
__device__ __forceinline__ void mma16816h(float c[4], uint32_t a0, uint32_t a1,
                                          uint32_t a2, uint32_t a3,
                                          uint32_t b0, uint32_t b1) {
    asm volatile(
        "mma.sync.aligned.m16n8k16.row.col.f32.f16.f16.f32 "
        "{%0,%1,%2,%3}, {%4,%5,%6,%7}, {%8,%9}, {%0,%1,%2,%3};"
        : "+f"(c[0]), "+f"(c[1]), "+f"(c[2]), "+f"(c[3])
        : "r"(a0), "r"(a1), "r"(a2), "r"(a3), "r"(b0), "r"(b1));
}
__device__ __forceinline__ void cpasync16(uint32_t dst, const void* src) {
    asm volatile("cp.async.cg.shared.global [%0], [%1], 16;" :: "r"(dst), "l"(src));
}
__device__ __forceinline__ void cp_commit() {
    asm volatile("cp.async.commit_group;");
}
template<int N> __device__ __forceinline__ void cp_wait() {
    asm volatile("cp.async.wait_group %0;" :: "n"(N));
}
__device__ __forceinline__ void unpack8(const uint4& w, float* f) {
    float2 p;
    p = __half22float2(*reinterpret_cast<const __half2*>(&w.x)); f[0]=p.x; f[1]=p.y;
    p = __half22float2(*reinterpret_cast<const __half2*>(&w.y)); f[2]=p.x; f[3]=p.y;
    p = __half22float2(*reinterpret_cast<const __half2*>(&w.z)); f[4]=p.x; f[5]=p.y;
    p = __half22float2(*reinterpret_cast<const __half2*>(&w.w)); f[6]=p.x; f[7]=p.y;
}

// ================= mega prep kernel (role by blockIdx range) =================
#define PB_ZERO 63
#define PB_GX   4000
#define PB_GEA  16000
#define PB_CVT  256
#define PB_W1   256
#define PB_WP   64
#define PB_IH   768
#define PB_WHH  96
#define PB_BIAS 16

__device__ __forceinline__ void convT_body(const float* __restrict__ W,
                                           __half* __restrict__ bh,
                                           int K, int N, int k0, int n0, int t) {
    __shared__ float tile[32][33];
    int tx = t & 31, ty = t >> 5;
#pragma unroll
    for (int j = 0; j < 4; j++)
        tile[ty + 8*j][tx] = W[(size_t)(k0 + ty + 8*j) * N + n0 + tx];
    __syncthreads();
#pragma unroll
    for (int j = 0; j < 4; j++)
        bh[(size_t)(n0 + ty + 8*j) * K + k0 + tx] = __float2half_rn(tile[tx][ty + 8*j]);
}
__device__ __forceinline__ void gather_body(__half* __restrict__ dst,
                                            const float* __restrict__ emb,
                                            const int* __restrict__ idx,
                                            int row, int lt) {
    int tok = idx[row];
    float4 f = *(const float4*)(emb + (size_t)tok*DD + 4*lt);
    __half2 p0 = __floats2half2_rn(f.x, f.y);
    __half2 p1 = __floats2half2_rn(f.z, f.w);
    uint2 o;
    o.x = *reinterpret_cast<uint32_t*>(&p0);
    o.y = *reinterpret_cast<uint32_t*>(&p1);
    *(uint2*)(dst + (size_t)row*DD + 4*lt) = o;
}

__global__ void prep_k(const int* __restrict__ node_tokens, const int* __restrict__ edge_tokens,
                       const float* __restrict__ emb,
                       const float* __restrict__ Wq, const float* __restrict__ Wk,
                       const float* __restrict__ Wv, const float* __restrict__ Wsk,
                       const float* __restrict__ We, const float* __restrict__ W1,
                       const float* __restrict__ Wp, const float* __restrict__ W_ih,
                       const float* __restrict__ W_hh,
                       const float* __restrict__ bq, const float* __restrict__ bk,
                       const float* __restrict__ bv, const float* __restrict__ bsk) {
    int bid = blockIdx.x, t = threadIdx.x;
    if (bid < PB_ZERO) {                                  // zero cnt
        int i = bid*256 + t;
        if (i < BB*NN) g_cnt[i] = 0;
        return;
    }
    bid -= PB_ZERO;
    if (bid < PB_GX) {                                    // gather node emb
        gather_body(g_x, emb, node_tokens, bid*4 + (t >> 6), t & 63);
        return;
    }
    bid -= PB_GX;
    if (bid < PB_GEA) {                                   // gather edge emb
        gather_body(g_ea, emb, edge_tokens, bid*4 + (t >> 6), t & 63);
        return;
    }
    bid -= PB_GEA;
    if (bid < 5*PB_CVT) {                                 // Wq/Wk/Wv/Wsk/We [256,1024]
        int w = bid / PB_CVT, r = bid % PB_CVT;
        const float* W = (w==0) ? Wq : (w==1) ? Wk : (w==2) ? Wv : (w==3) ? Wsk : We;
        __half* dst = (w==4) ? g_bE : (g_bN + (size_t)w*1024*DD);
        convT_body(W, dst, DD, HD, (r & 7)*32, (r >> 3)*32, t);
        return;
    }
    bid -= 5*PB_CVT;
    if (bid < PB_W1) {                                    // W1 [1024,256]
        convT_body(W1, g_bw1, HD, DD, (bid & 31)*32, (bid >> 5)*32, t);
        return;
    }
    bid -= PB_W1;
    if (bid < PB_WP) {                                    // Wp [256,256]
        convT_body(Wp, g_bwp, DD, DD, (bid & 7)*32, (bid >> 3)*32, t);
        return;
    }
    bid -= PB_WP;
    if (bid < PB_IH) {                                    // W_ih elementwise
        int i = bid*256 + t;
        g_bih[i] = __float2half_rn(W_ih[i]);
        return;
    }
    bid -= PB_IH;
    if (bid < PB_WHH) {                                   // pack W_hh (j8,g,8)
        int sub = t >> 5, j8 = t & 31;
        int g = bid*8 + sub;
        float4 a = *(const float4*)(W_hh + (size_t)g*DD + 8*j8);
        float4 b = *(const float4*)(W_hh + (size_t)g*DD + 8*j8 + 4);
        __half2 h0 = __floats2half2_rn(a.x, a.y);
        __half2 h1 = __floats2half2_rn(a.z, a.w);
        __half2 h2 = __floats2half2_rn(b.x, b.y);
        __half2 h3 = __floats2half2_rn(b.z, b.w);
        uint4 o;
        o.x = *reinterpret_cast<uint32_t*>(&h0);
        o.y = *reinterpret_cast<uint32_t*>(&h1);
        o.z = *reinterpret_cast<uint32_t*>(&h2);
        o.w = *reinterpret_cast<uint32_t*>(&h3);
        *(uint4*)(g_Wh8 + ((size_t)j8*G3 + g)*8) = o;
        return;
    }
    bid -= PB_WHH;
    {                                                     // bias concat
        int i = bid*256 + t;
        const float* src = (i < 1024) ? bq : (i < 2048) ? bk : (i < 3072) ? bv : bsk;
        g_biasN[i] = src[i & 1023];
    }
}
#define PREP_BLOCKS (PB_ZERO + PB_GX + PB_GEA + 5*PB_CVT + PB_W1 + PB_WP + PB_IH + PB_WHH + PB_BIAS)

// ================= single-pass fp16 mma GEMM core =================
#define KC 32
#define RSB 80
#define STG_A 0
#define STG_B 10240
#define STAGE_SZ 20480
#define NSTAGE 4
#define GEMM_SMEM (NSTAGE*STAGE_SZ)

template<int CRELU, int OUTMODE>
__device__ __forceinline__ void gemm_core(
    char* smc, const __half* __restrict__ A, const __half* __restrict__ Bw,
    const float* __restrict__ bias, float* __restrict__ C,
    __half* __restrict__ Ch, int Nld, int K, int bm, int bn) {
    const uint32_t smb = smem_to_u32(smc);
    const int t = threadIdx.x, lane = t & 31, warp = t >> 5;
    const int wm = (warp >> 2) * 64, wn = (warp & 3) * 32;

    const int fr = t >> 1, fk = (t & 1) * 16;
    const __half* Ap = A  + (size_t)(bm + fr) * K + fk;
    const __half* Bp = Bw + (size_t)(bn + fr) * K + fk;
    const uint32_t fillOff = smb + (uint32_t)(fr * RSB + fk * 2);

    const uint32_t aBase = smb + (uint32_t)(wm + (lane & 15)) * RSB + (uint32_t)(lane >> 4) * 16;
    const uint32_t bBase = smb + (uint32_t)(wn + ((lane >> 4) << 3) + (lane & 7)) * RSB
                               + (uint32_t)((lane >> 3) & 1) * 16;

    float acc[4][4][4];
#pragma unroll
    for (int i = 0; i < 4; i++)
#pragma unroll
        for (int j = 0; j < 4; j++)
#pragma unroll
            for (int k = 0; k < 4; k++) acc[i][j][k] = 0.f;

    const int NC = K / KC;
#pragma unroll
    for (int c = 0; c < NSTAGE - 1; c++) {
        uint32_t d = fillOff + (uint32_t)(c * STAGE_SZ);
        const __half* a0 = Ap + c * KC;
        const __half* b0 = Bp + c * KC;
        cpasync16(d + STG_A,      a0);
        cpasync16(d + STG_A + 16, a0 + 8);
        cpasync16(d + STG_B,      b0);
        cpasync16(d + STG_B + 16, b0 + 8);
        cp_commit();
    }

    for (int c = 0; c < NC; c++) {
        cp_wait<NSTAGE - 2>();
        __syncthreads();
        const uint32_t stg = (uint32_t)((c & (NSTAGE - 1)) * STAGE_SZ);
#pragma unroll
        for (int ks = 0; ks < 2; ks++) {
            const uint32_t kb = (uint32_t)(ks * 32);
            uint32_t br[2][4];
#pragma unroll
            for (int nb = 0; nb < 2; nb++)
                ldsm4(br[nb], bBase + stg + STG_B + (uint32_t)(nb * 16 * RSB) + kb);
            uint32_t ar[4][4];
#pragma unroll
            for (int mi = 0; mi < 4; mi++)
                ldsm4(ar[mi], aBase + stg + STG_A + (uint32_t)(mi * 16 * RSB) + kb);
#pragma unroll
            for (int mi = 0; mi < 4; mi++)
#pragma unroll
                for (int ni = 0; ni < 4; ni++)
                    mma16816h(acc[mi][ni], ar[mi][0], ar[mi][1], ar[mi][2], ar[mi][3],
                              br[ni>>1][(ni&1)*2], br[ni>>1][(ni&1)*2+1]);
        }
        __syncthreads();
        const int nx = c + NSTAGE - 1;
        if (nx < NC) {
            uint32_t d = fillOff + (uint32_t)((nx & (NSTAGE - 1)) * STAGE_SZ);
            const __half* a0 = Ap + nx * KC;
            const __half* b0 = Bp + nx * KC;
            cpasync16(d + STG_A,      a0);
            cpasync16(d + STG_A + 16, a0 + 8);
            cpasync16(d + STG_B,      b0);
            cpasync16(d + STG_B + 16, b0 + 8);
        }
        cp_commit();
    }

#pragma unroll
    for (int mi = 0; mi < 4; mi++) {
        const int r0 = bm + wm + mi*16 + (lane >> 2);
#pragma unroll
        for (int ni = 0; ni < 4; ni++) {
            const int col = bn + wn + ni*8 + (lane & 3)*2;
            float bx = 0.f, by = 0.f;
            if (bias) { bx = bias[col]; by = bias[col+1]; }
            float v0 = acc[mi][ni][0] + bx, v1 = acc[mi][ni][1] + by;
            float v2 = acc[mi][ni][2] + bx, v3 = acc[mi][ni][3] + by;
            if (CRELU) {
                v0 = fmaxf(v0, 0.f); v1 = fmaxf(v1, 0.f);
                v2 = fmaxf(v2, 0.f); v3 = fmaxf(v3, 0.f);
            }
            if (OUTMODE == 0) {
                *(float2*)(C + (size_t)r0 * Nld + col) = make_float2(v0, v1);
                *(float2*)(C + (size_t)(r0+8) * Nld + col) = make_float2(v2, v3);
            } else {
                __half2 p0 = __floats2half2_rn(v0, v1);
                __half2 p1 = __floats2half2_rn(v2, v3);
                *(uint32_t*)(Ch + (size_t)r0 * Nld + col) = *reinterpret_cast<uint32_t*>(&p0);
                *(uint32_t*)(Ch + (size_t)(r0+8) * Nld + col) = *reinterpret_cast<uint32_t*>(&p1);
            }
        }
    }
}

template<int CRELU, int OUTMODE>
__global__ __launch_bounds__(256, 1) void mmagemm_k(
    const __half* __restrict__ A, const __half* __restrict__ Bw,
    const float* __restrict__ bias, float* __restrict__ C,
    __half* __restrict__ Ch, int Nld, int K) {
    extern __shared__ char smc[];
    gemm_core<CRELU, OUTMODE>(smc, A, Bw, bias, C, Ch, Nld, K,
                              blockIdx.y * 128, blockIdx.x * 128);
}

// combined edge + qkvs GEMM (both fp16 out, K=256)
__global__ __launch_bounds__(256, 1) void gemm_big_k() {
    extern __shared__ char smc[];
    int cta = blockIdx.x;
    if (cta < 4000) {
        gemm_core<0, 1>(smc, g_ea, g_bE, nullptr, nullptr, g_e,
                        HD, DD, (cta >> 3) * 128, (cta & 7) * 128);
    } else {
        int r = cta - 4000;
        gemm_core<0, 1>(smc, g_x, g_bN, g_biasN, nullptr, g_qkvs,
                        QKVS_W, DD, (r >> 5) * 128, (r & 31) * 128);
    }
}

// ================= CSR build over dst =================
__global__ void count_k(const int* __restrict__ ei) {
    int i = blockIdx.x * blockDim.x + threadIdx.x;
    if (i >= BB*EE) return;
    int b = i / EE, e = i % EE;
    int dst = ei[(b*2 + 1)*EE + e];
    atomicAdd(&g_cnt[b*NN + dst], 1);
}
__global__ void scan_k() {   // grid BB, block 1024
    __shared__ int s[1024];
    int b = blockIdx.x, t = threadIdx.x;
    int v = (t < NN) ? g_cnt[b*NN + t] : 0;
    s[t] = v;
    __syncthreads();
    for (int d = 1; d < 1024; d <<= 1) {
        int x = (t >= d) ? s[t - d] : 0;
        __syncthreads();
        s[t] += x;
        __syncthreads();
    }
    if (t < NN) {
        int excl = s[t] - v;
        g_off[b*NN + t] = excl;
        g_cur[b*NN + t] = excl;
    }
}
__global__ void fill_k(const int* __restrict__ ei) {
    int i = blockIdx.x * blockDim.x + threadIdx.x;
    if (i >= BB*EE) return;
    int b = i / EE, e = i % EE;
    int dst = ei[(b*2 + 1)*EE + e];
    int pos = atomicAdd(&g_cur[b*NN + dst], 1);
    g_eord[b*EE + pos] = e;
}

// ================= fused attention: 2-way edge interleave, online softmax =================
__global__ __launch_bounds__(256) void attn_fused_k(const int* __restrict__ ei) {
    int g = blockIdx.x * 8 + (threadIdx.x >> 5);
    int lane = threadIdx.x & 31;
    if (g >= BB*NN*NH) return;
    int h = g & 3, bn = g >> 2;
    int b = bn / NN;
    int deg = g_cnt[bn], off = g_off[bn];
    const int off_b = b*EE + off;
    const int* srcRow = ei + (b*2)*EE;
    const int dOff = h*DD + 8*lane;

    float q[8];
    unpack8(*(const uint4*)(g_qkvs + (size_t)bn*QKVS_W + dOff), q);

    float m0 = -3.0e38f, den0 = 0.f, m1 = -3.0e38f, den1 = 0.f;
    float o0[8], o1[8];
#pragma unroll
    for (int r = 0; r < 8; r++) { o0[r] = 0.f; o1[r] = 0.f; }

    int e0 = 0, s0 = 0, e1 = 0, s1 = 0;
    if (deg > 0) { e0 = g_eord[off_b];     s0 = srcRow[e0]; }
    if (deg > 1) { e1 = g_eord[off_b + 1]; s1 = srcRow[e1]; }

    for (int i = 0; i < deg; i += 2) {
        const bool has1 = (i + 1 < deg);
        const __half* b0p = g_qkvs + (size_t)(b*NN + s0)*QKVS_W + dOff;
        uint4 kw0 = *(const uint4*)(b0p + HD);
        uint4 vw0 = *(const uint4*)(b0p + 2*HD);
        uint4 ew0 = *(const uint4*)(g_e + (size_t)(b*EE + e0)*HD + dOff);
        uint4 kw1, vw1, ew1;
        if (has1) {
            const __half* b1p = g_qkvs + (size_t)(b*NN + s1)*QKVS_W + dOff;
            kw1 = *(const uint4*)(b1p + HD);
            vw1 = *(const uint4*)(b1p + 2*HD);
            ew1 = *(const uint4*)(g_e + (size_t)(b*EE + e1)*HD + dOff);
        }
        // prefetch next pair's indices
        if (i + 2 < deg) { e0 = g_eord[off_b + i + 2]; s0 = srcRow[e0]; }
        if (i + 3 < deg) { e1 = g_eord[off_b + i + 3]; s1 = srcRow[e1]; }
        {
            float kf[8], vf[8], ef[8];
            unpack8(kw0, kf); unpack8(vw0, vf); unpack8(ew0, ef);
            float a = 0.f;
#pragma unroll
            for (int r = 0; r < 8; r++) a += q[r] * (kf[r] + ef[r]);
#pragma unroll
            for (int dlt = 16; dlt; dlt >>= 1) a += __shfl_xor_sync(0xffffffffu, a, dlt);
            a *= 0.0625f;
            float mn = fmaxf(m0, a);
            float sc = expf(m0 - mn);
            float w = expf(a - mn);
            den0 = den0 * sc + w;
#pragma unroll
            for (int r = 0; r < 8; r++) o0[r] = o0[r] * sc + w * (vf[r] + ef[r]);
            m0 = mn;
        }
        if (has1) {
            float kf[8], vf[8], ef[8];
            unpack8(kw1, kf); unpack8(vw1, vf); unpack8(ew1, ef);
            float a = 0.f;
#pragma unroll
            for (int r = 0; r < 8; r++) a += q[r] * (kf[r] + ef[r]);
#pragma unroll
            for (int dlt = 16; dlt; dlt >>= 1) a += __shfl_xor_sync(0xffffffffu, a, dlt);
            a *= 0.0625f;
            float mn = fmaxf(m1, a);
            float sc = expf(m1 - mn);
            float w = expf(a - mn);
            den1 = den1 * sc + w;
#pragma unroll
            for (int r = 0; r < 8; r++) o1[r] = o1[r] * sc + w * (vf[r] + ef[r]);
            m1 = mn;
        }
    }
    // merge the two online-softmax states
    float mm = fmaxf(m0, m1);
    float sc0 = expf(m0 - mm), sc1 = expf(m1 - mm);
    float den = den0 * sc0 + den1 * sc1;
    float invden = (deg > 0) ? (1.f / den) : 0.f;

    float sk[8];
    unpack8(*(const uint4*)(g_qkvs + (size_t)bn*QKVS_W + 3*HD + dOff), sk);
    __half2 hv[4];
#pragma unroll
    for (int r = 0; r < 4; r++) {
        float f0 = fmaxf(sk[2*r]   + (o0[2*r]   * sc0 + o1[2*r]   * sc1) * invden, 0.f);
        float f1 = fmaxf(sk[2*r+1] + (o0[2*r+1] * sc0 + o1[2*r+1] * sc1) * invden, 0.f);
        hv[r] = __floats2half2_rn(f0, f1);
    }
    *(uint4*)(g_h + (size_t)bn*HD + dOff) = *reinterpret_cast<uint4*>(hv);
}

// ================= inv path =================
__global__ void mixed_inv_k(const int* __restrict__ tok, const int* __restrict__ nod,
                            const float* __restrict__ emb) {
    int row = blockIdx.x, t = threadIdx.x;   // 128 threads
    int b = row / LL;
    int tk = tok[row], nd = nod[row];
    float2 f0 = *(const float2*)(emb + (size_t)tk*DD + 2*t);
    float2 f1 = __half22float2(*(const __half2*)(g_gr + (size_t)(b*NN + nd)*DD + 2*t));
    __half2 hv = __floats2half2_rn(f0.x + f1.x, f0.y + f1.y);
    *(uint32_t*)(g_inve + (size_t)row*DD + 2*t) = *reinterpret_cast<uint32_t*>(&hv);
}

// GRU: one block per batch, 384 threads, 2 gates/thread, W_hh fp16 packed
__global__ void gru_k(const float* __restrict__ b_hh) {
    __shared__ float hs[256];
    __shared__ float ghs[768];
    int b = blockIdx.x, t = threadIdx.x;  // 384 threads
    if (t < 256) hs[t] = 0.f;
    float bh0 = b_hh[t], bh1 = b_hh[t + 384];
    const uint4* W = (const uint4*)g_Wh8;
    __syncthreads();
    for (int l = 0; l < LL; l++) {
        float acc0 = bh0, acc1 = bh1;
#pragma unroll 8
        for (int j8 = 0; j8 < 32; j8++) {
            uint4 w0 = W[j8 * G3 + t];
            uint4 w1 = W[j8 * G3 + t + 384];
            float4 h0 = *(const float4*)(hs + 8*j8);
            float4 h1 = *(const float4*)(hs + 8*j8 + 4);
            float2 p;
            p = __half22float2(*reinterpret_cast<__half2*>(&w0.x));
            acc0 += h0.x*p.x + h0.y*p.y;
            p = __half22float2(*reinterpret_cast<__half2*>(&w0.y));
            acc0 += h0.z*p.x + h0.w*p.y;
            p = __half22float2(*reinterpret_cast<__half2*>(&w0.z));
            acc0 += h1.x*p.x + h1.y*p.y;
            p = __half22float2(*reinterpret_cast<__half2*>(&w0.w));
            acc0 += h1.z*p.x + h1.w*p.y;
            p = __half22float2(*reinterpret_cast<__half2*>(&w1.x));
            acc1 += h0.x*p.x + h0.y*p.y;
            p = __half22float2(*reinterpret_cast<__half2*>(&w1.y));
            acc1 += h0.z*p.x + h0.w*p.y;
            p = __half22float2(*reinterpret_cast<__half2*>(&w1.z));
            acc1 += h1.x*p.x + h1.y*p.y;
            p = __half22float2(*reinterpret_cast<__half2*>(&w1.w));
            acc1 += h1.z*p.x + h1.w*p.y;
        }
        ghs[t] = acc0;
        ghs[t + 384] = acc1;
        __syncthreads();
        float hn = 0.f;
        if (t < 256) {
            const float* g = g_gx + (size_t)(b*LL + l)*G3;
            float r = 1.f / (1.f + expf(-(g[t]       + ghs[t])));
            float z = 1.f / (1.f + expf(-(g[256 + t] + ghs[256 + t])));
            float c = tanhf(g[512 + t] + r * ghs[512 + t]);
            hn = (1.f - z) * c + z * hs[t];
        }
        __syncthreads();
        if (t < 256) hs[t] = hn;
        __syncthreads();
    }
    if (t < 256) g_invvec[b*OO + t] = hs[t];
}

// ================= scoring =================
__global__ void score_k(const float* __restrict__ Wap, const float* __restrict__ bap,
                        const float* __restrict__ Wab, const float* __restrict__ bab,
                        const int* __restrict__ aa_token, const int* __restrict__ aa_node,
                        const float* __restrict__ mask, const float* __restrict__ emb,
                        float* __restrict__ out) {
    __shared__ float invs[256];
    __shared__ float u[256];
    __shared__ float red[256];
    int b = blockIdx.x, t = threadIdx.x;
    int warp = t >> 5, lane = t & 31;
    invs[t] = g_invvec[b*OO + t];
    __syncthreads();
    for (int d = warp*32; d < warp*32 + 32; d++) {
        float acc = 0.f;
#pragma unroll
        for (int r = 0; r < 8; r++) {
            int o = lane + 32*r;
            acc += Wap[(size_t)d*OO + o] * invs[o];
        }
#pragma unroll
        for (int dd = 16; dd; dd >>= 1) acc += __shfl_xor_sync(0xffffffffu, acc, dd);
        if (lane == 0) u[d] = acc + Wab[d];
    }
    red[t] = bap[t] * invs[t];
    __syncthreads();
    for (int s = 128; s; s >>= 1) {
        if (t < s) red[t] += red[t + s];
        __syncthreads();
    }
    float cb = red[0] + bab[0];
    for (int a = warp; a < ACT; a += 8) {
        int tok = aa_token[b*ACT + a], nod = aa_node[b*ACT + a];
        const float* er = emb + (size_t)tok*DD;
        const __half* gg = g_gr + (size_t)(b*NN + nod)*DD;
        float acc = 0.f;
#pragma unroll
        for (int r = 0; r < 8; r++) {
            int d = lane + 32*r;
            acc += (er[d] + __half2float(gg[d])) * u[d];
        }
#pragma unroll
        for (int dd = 16; dd; dd >>= 1) acc += __shfl_xor_sync(0xffffffffu, acc, dd);
        if (lane == 0) {
            float mk = mask[b*ACT + a];
            float lm = fmaxf(logf(mk), -FLT_MAX);
            out[b*ACT + a] = acc + cb + lm;
        }
    }
}

// ================= host launcher =================
extern "C" void kernel_launch(void* const* d_in, const int* in_sizes, int n_in,
                              void* d_out, int out_size) {
    const int*   node_tokens = (const int*)d_in[0];
    const int*   edge_tokens = (const int*)d_in[1];
    const int*   edge_index  = (const int*)d_in[2];
    const int*   inv_token   = (const int*)d_in[3];
    const int*   inv_node    = (const int*)d_in[4];
    const int*   aa_token    = (const int*)d_in[5];
    const int*   aa_node     = (const int*)d_in[6];
    const float* action_mask = (const float*)d_in[7];
    const float* emb         = (const float*)d_in[8];
    const float* Wq  = (const float*)d_in[9];
    const float* bq  = (const float*)d_in[10];
    const float* Wk  = (const float*)d_in[11];
    const float* bk  = (const float*)d_in[12];
    const float* Wv  = (const float*)d_in[13];
    const float* bv  = (const float*)d_in[14];
    const float* We  = (const float*)d_in[15];
    const float* Wsk = (const float*)d_in[16];
    const float* bsk = (const float*)d_in[17];
    const float* W1  = (const float*)d_in[18];
    const float* b1  = (const float*)d_in[19];
    const float* Wp  = (const float*)d_in[20];
    const float* bp  = (const float*)d_in[21];
    const float* W_ih = (const float*)d_in[22];
    const float* W_hh = (const float*)d_in[23];
    const float* b_ih = (const float*)d_in[24];
    const float* b_hh = (const float*)d_in[25];
    const float* Wab = (const float*)d_in[26];
    const float* bab = (const float*)d_in[27];
    const float* Wap = (const float*)d_in[28];
    const float* bap = (const float*)d_in[29];
    float* out = (float*)d_out;

    void* p;
    __half *h_, *gr_, *inve_, *invh_, *bw1, *bwp, *bih;
    float *gx_;
    cudaGetSymbolAddress(&p, g_h);     h_ = (__half*)p;
    cudaGetSymbolAddress(&p, g_gr);    gr_ = (__half*)p;
    cudaGetSymbolAddress(&p, g_inve);  inve_ = (__half*)p;
    cudaGetSymbolAddress(&p, g_invh);  invh_ = (__half*)p;
    cudaGetSymbolAddress(&p, g_gx);    gx_ = (float*)p;
    cudaGetSymbolAddress(&p, g_bw1);   bw1 = (__half*)p;
    cudaGetSymbolAddress(&p, g_bwp);   bwp = (__half*)p;
    cudaGetSymbolAddress(&p, g_bih);   bih = (__half*)p;

    cudaFuncSetAttribute(gemm_big_k,      cudaFuncAttributeMaxDynamicSharedMemorySize, GEMM_SMEM);
    cudaFuncSetAttribute(mmagemm_k<1,0>,  cudaFuncAttributeMaxDynamicSharedMemorySize, GEMM_SMEM);
    cudaFuncSetAttribute(mmagemm_k<1,1>,  cudaFuncAttributeMaxDynamicSharedMemorySize, GEMM_SMEM);
    cudaFuncSetAttribute(mmagemm_k<0,0>,  cudaFuncAttributeMaxDynamicSharedMemorySize, GEMM_SMEM);

    // 1: all gathers + weight conversions + cnt zero, one launch
    prep_k<<<PREP_BLOCKS, 256>>>(node_tokens, edge_tokens, emb,
                                 Wq, Wk, Wv, Wsk, We, W1, Wp, W_ih, W_hh,
                                 bq, bk, bv, bsk);
    // 2-4: CSR
    count_k<<<(BB*EE + 255)/256, 256>>>(edge_index);
    scan_k<<<BB, 1024>>>();
    fill_k<<<(BB*EE + 255)/256, 256>>>(edge_index);
    // 5: combined edge + qkvs GEMM
    gemm_big_k<<<8000, 256, GEMM_SMEM>>>();
    // 6: fused attention + skip + relu -> fp16 h
    attn_fused_k<<<(BB*NN*NH + 7)/8, 256>>>(edge_index);
    // 7: graph_repr = relu(h@W1 + b1) -> fp16
    dim3 ggr(DD/128, (BB*NN)/128);
    mmagemm_k<1,1><<<ggr, 256, GEMM_SMEM>>>(h_, bw1, b1, nullptr, gr_, DD, HD);
    // 8-11: inv path
    mixed_inv_k<<<BB*LL, 128>>>(inv_token, inv_node, emb);
    dim3 ginv(DD/128, (BB*LL)/128);
    mmagemm_k<1,1><<<ginv, 256, GEMM_SMEM>>>(inve_, bwp, bp, nullptr, invh_, DD, DD);
    dim3 ggx(G3/128, (BB*LL)/128);
    mmagemm_k<0,0><<<ggx, 256, GEMM_SMEM>>>(invh_, bih, b_ih, gx_, nullptr, G3, DD);
    gru_k<<<BB, 384>>>(b_hh);
    // 12: scores
    score_k<<<BB, 256>>>(Wap, bap, Wab, bab, aa_token, aa_node, action_mask, emb, out);
    (void)in_sizes; (void)n_in; (void)out_size;
}

// round 14
// speedup vs baseline: 1.0467x; 1.0467x over previous
#include <cuda_runtime.h>
#include <cuda_fp16.h>
#include <math.h>
#include <float.h>
#include <stdint.h>

// Problem constants
#define BB 16
#define NN 1000
#define EE 4000
#define DD 256
#define NH 4
#define HD 1024
#define LL 64
#define ACT 128
#define OO 256
#define G3 768
#define QKVS_W 4096

// ================= scratch (device globals) =================
__device__ __align__(16) __half g_x[BB*NN*DD];
__device__ __align__(16) __half g_ea[BB*EE*DD];
__device__ __align__(16) __half g_qkvs[(size_t)BB*NN*QKVS_W];  // q|k|v|skip fp16
__device__ __align__(16) __half g_e[(size_t)BB*EE*HD];
__device__ __align__(16) __half g_h[(size_t)BB*NN*HD];
__device__ __align__(16) __half g_gr[BB*NN*DD];                // fp16 graph_repr
__device__ int   g_cnt[BB*NN];
__device__ int   g_off[BB*NN];
__device__ int   g_cur[BB*NN];
__device__ int   g_eord[BB*EE];
__device__ __align__(16) __half g_inve[BB*LL*DD];
__device__ __align__(16) __half g_invh[BB*LL*DD];
__device__ __align__(16) float g_gx[BB*LL*G3];
__device__ __align__(16) __half g_Wh8[DD*G3];   // W_hh fp16 packed (j8, g, 8)
__device__ float g_invvec[BB*OO];
__device__ float g_biasN[QKVS_W];
// fp16 weight buffers, [N,K] layout (k contiguous)
__device__ __align__(16) __half g_bN[QKVS_W*DD];
__device__ __align__(16) __half g_bE[HD*DD];
__device__ __align__(16) __half g_bw1[DD*HD];
__device__ __align__(16) __half g_bwp[DD*DD];
__device__ __align__(16) __half g_bih[G3*DD];

// ================= helpers =================
__device__ __forceinline__ uint32_t smem_to_u32(const void* smem_ptr) {
    uint32_t addr;
    asm("{ .reg .u64 tmp; cvta.to.shared.u64 tmp, %1; cvt.u32.u64 %0, tmp; }"
        : "=r"(addr) : "l"(smem_ptr));
    return addr;
}
__device__ __forceinline__ void ldsm4(uint32_t r[4], uint32_t addr) {
    asm volatile("ldmatrix.sync.aligned.m8n8.x4.shared.b16 {%0,%1,%2,%3}, [%4];"
        : "=r"(r[0]), "=r"(r[1]), "=r"(r[2]), "=r"(r[3]) : "r"(addr));
}
__device__ __forceinline__ void mma16816h(float c[4], uint32_t a0, uint32_t a1,
                                          uint32_t a2, uint32_t a3,
                                          uint32_t b0, uint32_t b1) {
    asm volatile(
        "mma.sync.aligned.m16n8k16.row.col.f32.f16.f16.f32 "
        "{%0,%1,%2,%3}, {%4,%5,%6,%7}, {%8,%9}, {%0,%1,%2,%3};"
        : "+f"(c[0]), "+f"(c[1]), "+f"(c[2]), "+f"(c[3])
        : "r"(a0), "r"(a1), "r"(a2), "r"(a3), "r"(b0), "r"(b1));
}
__device__ __forceinline__ void cpasync16(uint32_t dst, const void* src) {
    asm volatile("cp.async.cg.shared.global [%0], [%1], 16;" :: "r"(dst), "l"(src));
}
__device__ __forceinline__ void cp_commit() {
    asm volatile("cp.async.commit_group;");
}
template<int N> __device__ __forceinline__ void cp_wait() {
    asm volatile("cp.async.wait_group %0;" :: "n"(N));
}
__device__ __forceinline__ void unpack8(const uint4& w, float* f) {
    float2 p;
    p = __half22float2(*reinterpret_cast<const __half2*>(&w.x)); f[0]=p.x; f[1]=p.y;
    p = __half22float2(*reinterpret_cast<const __half2*>(&w.y)); f[2]=p.x; f[3]=p.y;
    p = __half22float2(*reinterpret_cast<const __half2*>(&w.z)); f[4]=p.x; f[5]=p.y;
    p = __half22float2(*reinterpret_cast<const __half2*>(&w.w)); f[6]=p.x; f[7]=p.y;
}

// ================= mega prep kernel (role by blockIdx range) =================
#define PB_ZERO 63
#define PB_GX   4000
#define PB_GEA  16000
#define PB_CVT  256
#define PB_W1   256
#define PB_WP   64
#define PB_IH   768
#define PB_WHH  96
#define PB_BIAS 16

__device__ __forceinline__ void convT_body(const float* __restrict__ W,
                                           __half* __restrict__ bh,
                                           int K, int N, int k0, int n0, int t) {
    __shared__ float tile[32][33];
    int tx = t & 31, ty = t >> 5;
#pragma unroll
    for (int j = 0; j < 4; j++)
        tile[ty + 8*j][tx] = W[(size_t)(k0 + ty + 8*j) * N + n0 + tx];
    __syncthreads();
#pragma unroll
    for (int j = 0; j < 4; j++)
        bh[(size_t)(n0 + ty + 8*j) * K + k0 + tx] = __float2half_rn(tile[tx][ty + 8*j]);
}
__device__ __forceinline__ void gather_body(__half* __restrict__ dst,
                                            const float* __restrict__ emb,
                                            const int* __restrict__ idx,
                                            int row, int lt) {
    int tok = idx[row];
    float4 f = *(const float4*)(emb + (size_t)tok*DD + 4*lt);
    __half2 p0 = __floats2half2_rn(f.x, f.y);
    __half2 p1 = __floats2half2_rn(f.z, f.w);
    uint2 o;
    o.x = *reinterpret_cast<uint32_t*>(&p0);
    o.y = *reinterpret_cast<uint32_t*>(&p1);
    *(uint2*)(dst + (size_t)row*DD + 4*lt) = o;
}

__global__ void prep_k(const int* __restrict__ node_tokens, const int* __restrict__ edge_tokens,
                       const float* __restrict__ emb,
                       const float* __restrict__ Wq, const float* __restrict__ Wk,
                       const float* __restrict__ Wv, const float* __restrict__ Wsk,
                       const float* __restrict__ We, const float* __restrict__ W1,
                       const float* __restrict__ Wp, const float* __restrict__ W_ih,
                       const float* __restrict__ W_hh,
                       const float* __restrict__ bq, const float* __restrict__ bk,
                       const float* __restrict__ bv, const float* __restrict__ bsk) {
    int bid = blockIdx.x, t = threadIdx.x;
    if (bid < PB_ZERO) {                                  // zero cnt
        int i = bid*256 + t;
        if (i < BB*NN) g_cnt[i] = 0;
        return;
    }
    bid -= PB_ZERO;
    if (bid < PB_GX) {                                    // gather node emb
        gather_body(g_x, emb, node_tokens, bid*4 + (t >> 6), t & 63);
        return;
    }
    bid -= PB_GX;
    if (bid < PB_GEA) {                                   // gather edge emb
        gather_body(g_ea, emb, edge_tokens, bid*4 + (t >> 6), t & 63);
        return;
    }
    bid -= PB_GEA;
    if (bid < 5*PB_CVT) {                                 // Wq/Wk/Wv/Wsk/We [256,1024]
        int w = bid / PB_CVT, r = bid % PB_CVT;
        const float* W = (w==0) ? Wq : (w==1) ? Wk : (w==2) ? Wv : (w==3) ? Wsk : We;
        __half* dst = (w==4) ? g_bE : (g_bN + (size_t)w*1024*DD);
        convT_body(W, dst, DD, HD, (r & 7)*32, (r >> 3)*32, t);
        return;
    }
    bid -= 5*PB_CVT;
    if (bid < PB_W1) {                                    // W1 [1024,256]
        convT_body(W1, g_bw1, HD, DD, (bid & 31)*32, (bid >> 5)*32, t);
        return;
    }
    bid -= PB_W1;
    if (bid < PB_WP) {                                    // Wp [256,256]
        convT_body(Wp, g_bwp, DD, DD, (bid & 7)*32, (bid >> 3)*32, t);
        return;
    }
    bid -= PB_WP;
    if (bid < PB_IH) {                                    // W_ih elementwise
        int i = bid*256 + t;
        g_bih[i] = __float2half_rn(W_ih[i]);
        return;
    }
    bid -= PB_IH;
    if (bid < PB_WHH) {                                   // pack W_hh (j8,g,8)
        int sub = t >> 5, j8 = t & 31;
        int g = bid*8 + sub;
        float4 a = *(const float4*)(W_hh + (size_t)g*DD + 8*j8);
        float4 b = *(const float4*)(W_hh + (size_t)g*DD + 8*j8 + 4);
        __half2 h0 = __floats2half2_rn(a.x, a.y);
        __half2 h1 = __floats2half2_rn(a.z, a.w);
        __half2 h2 = __floats2half2_rn(b.x, b.y);
        __half2 h3 = __floats2half2_rn(b.z, b.w);
        uint4 o;
        o.x = *reinterpret_cast<uint32_t*>(&h0);
        o.y = *reinterpret_cast<uint32_t*>(&h1);
        o.z = *reinterpret_cast<uint32_t*>(&h2);
        o.w = *reinterpret_cast<uint32_t*>(&h3);
        *(uint4*)(g_Wh8 + ((size_t)j8*G3 + g)*8) = o;
        return;
    }
    bid -= PB_WHH;
    {                                                     // bias concat
        int i = bid*256 + t;
        const float* src = (i < 1024) ? bq : (i < 2048) ? bk : (i < 3072) ? bv : bsk;
        g_biasN[i] = src[i & 1023];
    }
}
#define PREP_BLOCKS (PB_ZERO + PB_GX + PB_GEA + 5*PB_CVT + PB_W1 + PB_WP + PB_IH + PB_WHH + PB_BIAS)

// ================= single-pass fp16 mma GEMM core =================
#define KC 32
#define RSB 80
#define STG_A 0
#define STG_B 10240
#define STAGE_SZ 20480
#define NSTAGE 4
#define GEMM_SMEM (NSTAGE*STAGE_SZ)

template<int CRELU, int OUTMODE>
__device__ __forceinline__ void gemm_core(
    char* smc, const __half* __restrict__ A, const __half* __restrict__ Bw,
    const float* __restrict__ bias, float* __restrict__ C,
    __half* __restrict__ Ch, int Nld, int K, int bm, int bn) {
    const uint32_t smb = smem_to_u32(smc);
    const int t = threadIdx.x, lane = t & 31, warp = t >> 5;
    const int wm = (warp >> 2) * 64, wn = (warp & 3) * 32;

    const int fr = t >> 1, fk = (t & 1) * 16;
    const __half* Ap = A  + (size_t)(bm + fr) * K + fk;
    const __half* Bp = Bw + (size_t)(bn + fr) * K + fk;
    const uint32_t fillOff = smb + (uint32_t)(fr * RSB + fk * 2);

    const uint32_t aBase = smb + (uint32_t)(wm + (lane & 15)) * RSB + (uint32_t)(lane >> 4) * 16;
    const uint32_t bBase = smb + (uint32_t)(wn + ((lane >> 4) << 3) + (lane & 7)) * RSB
                               + (uint32_t)((lane >> 3) & 1) * 16;

    float acc[4][4][4];
#pragma unroll
    for (int i = 0; i < 4; i++)
#pragma unroll
        for (int j = 0; j < 4; j++)
#pragma unroll
            for (int k = 0; k < 4; k++) acc[i][j][k] = 0.f;

    const int NC = K / KC;
#pragma unroll
    for (int c = 0; c < NSTAGE - 1; c++) {
        uint32_t d = fillOff + (uint32_t)(c * STAGE_SZ);
        const __half* a0 = Ap + c * KC;
        const __half* b0 = Bp + c * KC;
        cpasync16(d + STG_A,      a0);
        cpasync16(d + STG_A + 16, a0 + 8);
        cpasync16(d + STG_B,      b0);
        cpasync16(d + STG_B + 16, b0 + 8);
        cp_commit();
    }

    for (int c = 0; c < NC; c++) {
        cp_wait<NSTAGE - 2>();
        __syncthreads();
        const uint32_t stg = (uint32_t)((c & (NSTAGE - 1)) * STAGE_SZ);
#pragma unroll
        for (int ks = 0; ks < 2; ks++) {
            const uint32_t kb = (uint32_t)(ks * 32);
            uint32_t br[2][4];
#pragma unroll
            for (int nb = 0; nb < 2; nb++)
                ldsm4(br[nb], bBase + stg + STG_B + (uint32_t)(nb * 16 * RSB) + kb);
            uint32_t ar[4][4];
#pragma unroll
            for (int mi = 0; mi < 4; mi++)
                ldsm4(ar[mi], aBase + stg + STG_A + (uint32_t)(mi * 16 * RSB) + kb);
#pragma unroll
            for (int mi = 0; mi < 4; mi++)
#pragma unroll
                for (int ni = 0; ni < 4; ni++)
                    mma16816h(acc[mi][ni], ar[mi][0], ar[mi][1], ar[mi][2], ar[mi][3],
                              br[ni>>1][(ni&1)*2], br[ni>>1][(ni&1)*2+1]);
        }
        __syncthreads();
        const int nx = c + NSTAGE - 1;
        if (nx < NC) {
            uint32_t d = fillOff + (uint32_t)((nx & (NSTAGE - 1)) * STAGE_SZ);
            const __half* a0 = Ap + nx * KC;
            const __half* b0 = Bp + nx * KC;
            cpasync16(d + STG_A,      a0);
            cpasync16(d + STG_A + 16, a0 + 8);
            cpasync16(d + STG_B,      b0);
            cpasync16(d + STG_B + 16, b0 + 8);
        }
        cp_commit();
    }

#pragma unroll
    for (int mi = 0; mi < 4; mi++) {
        const int r0 = bm + wm + mi*16 + (lane >> 2);
#pragma unroll
        for (int ni = 0; ni < 4; ni++) {
            const int col = bn + wn + ni*8 + (lane & 3)*2;
            float bx = 0.f, by = 0.f;
            if (bias) { bx = bias[col]; by = bias[col+1]; }
            float v0 = acc[mi][ni][0] + bx, v1 = acc[mi][ni][1] + by;
            float v2 = acc[mi][ni][2] + bx, v3 = acc[mi][ni][3] + by;
            if (CRELU) {
                v0 = fmaxf(v0, 0.f); v1 = fmaxf(v1, 0.f);
                v2 = fmaxf(v2, 0.f); v3 = fmaxf(v3, 0.f);
            }
            if (OUTMODE == 0) {
                *(float2*)(C + (size_t)r0 * Nld + col) = make_float2(v0, v1);
                *(float2*)(C + (size_t)(r0+8) * Nld + col) = make_float2(v2, v3);
            } else {
                __half2 p0 = __floats2half2_rn(v0, v1);
                __half2 p1 = __floats2half2_rn(v2, v3);
                *(uint32_t*)(Ch + (size_t)r0 * Nld + col) = *reinterpret_cast<uint32_t*>(&p0);
                *(uint32_t*)(Ch + (size_t)(r0+8) * Nld + col) = *reinterpret_cast<uint32_t*>(&p1);
            }
        }
    }
}

template<int CRELU, int OUTMODE>
__global__ __launch_bounds__(256, 1) void mmagemm_k(
    const __half* __restrict__ A, const __half* __restrict__ Bw,
    const float* __restrict__ bias, float* __restrict__ C,
    __half* __restrict__ Ch, int Nld, int K) {
    extern __shared__ char smc[];
    gemm_core<CRELU, OUTMODE>(smc, A, Bw, bias, C, Ch, Nld, K,
                              blockIdx.y * 128, blockIdx.x * 128);
}

// combined edge + qkvs GEMM (both fp16 out, K=256)
__global__ __launch_bounds__(256, 1) void gemm_big_k() {
    extern __shared__ char smc[];
    int cta = blockIdx.x;
    if (cta < 4000) {
        gemm_core<0, 1>(smc, g_ea, g_bE, nullptr, nullptr, g_e,
                        HD, DD, (cta >> 3) * 128, (cta & 7) * 128);
    } else {
        int r = cta - 4000;
        gemm_core<0, 1>(smc, g_x, g_bN, g_biasN, nullptr, g_qkvs,
                        QKVS_W, DD, (r >> 5) * 128, (r & 31) * 128);
    }
}

// ================= CSR build over dst =================
__global__ void count_k(const int* __restrict__ ei) {
    int i = blockIdx.x * blockDim.x + threadIdx.x;
    if (i >= BB*EE) return;
    int b = i / EE, e = i % EE;
    int dst = ei[(b*2 + 1)*EE + e];
    atomicAdd(&g_cnt[b*NN + dst], 1);
}
__global__ void scan_k() {   // grid BB, block 1024
    __shared__ int s[1024];
    int b = blockIdx.x, t = threadIdx.x;
    int v = (t < NN) ? g_cnt[b*NN + t] : 0;
    s[t] = v;
    __syncthreads();
    for (int d = 1; d < 1024; d <<= 1) {
        int x = (t >= d) ? s[t - d] : 0;
        __syncthreads();
        s[t] += x;
        __syncthreads();
    }
    if (t < NN) {
        int excl = s[t] - v;
        g_off[b*NN + t] = excl;
        g_cur[b*NN + t] = excl;
    }
}
__global__ void fill_k(const int* __restrict__ ei) {
    int i = blockIdx.x * blockDim.x + threadIdx.x;
    if (i >= BB*EE) return;
    int b = i / EE, e = i % EE;
    int dst = ei[(b*2 + 1)*EE + e];
    int pos = atomicAdd(&g_cur[b*NN + dst], 1);
    g_eord[b*EE + pos] = e;
}

// ================= fused attention: uint4 loads + index prefetch (round-11 form) =================
__global__ void attn_fused_k(const int* __restrict__ ei) {
    int g = blockIdx.x * 4 + (threadIdx.x >> 5);
    int lane = threadIdx.x & 31;
    if (g >= BB*NN*NH) return;
    int h = g & 3, bn = g >> 2;
    int b = bn / NN;
    int deg = g_cnt[bn], off = g_off[bn];
    const int off_b = b*EE + off;
    const int* srcRow = ei + (b*2)*EE;

    const __half* qp = g_qkvs + (size_t)bn*QKVS_W + h*DD + 8*lane;
    float q[8];
    unpack8(*(const uint4*)qp, q);

    float m = -3.0e38f, den = 0.f;
    float o[8];
#pragma unroll
    for (int r = 0; r < 8; r++) o[r] = 0.f;

    int e_cur = 0, s_cur = 0;
    if (deg > 0) { e_cur = g_eord[off_b]; s_cur = srcRow[e_cur]; }
    for (int i = 0; i < deg; i++) {
        int e_nxt = 0, s_nxt = 0;
        if (i + 1 < deg) { e_nxt = g_eord[off_b + i + 1]; s_nxt = srcRow[e_nxt]; }
        const __half* base = g_qkvs + (size_t)(b*NN + s_cur)*QKVS_W + h*DD + 8*lane;
        uint4 kw = *(const uint4*)(base + HD);
        uint4 vw = *(const uint4*)(base + 2*HD);
        uint4 ew = *(const uint4*)(g_e + (size_t)(b*EE + e_cur)*HD + h*DD + 8*lane);
        float kf[8], vf[8], ef[8];
        unpack8(kw, kf); unpack8(vw, vf); unpack8(ew, ef);
        float a = 0.f;
#pragma unroll
        for (int r = 0; r < 8; r++) a += q[r] * (kf[r] + ef[r]);
#pragma unroll
        for (int dlt = 16; dlt; dlt >>= 1) a += __shfl_xor_sync(0xffffffffu, a, dlt);
        a *= 0.0625f;
        float mn = fmaxf(m, a);
        float scale = expf(m - mn);
        float w = expf(a - mn);
        den = den * scale + w;
#pragma unroll
        for (int r = 0; r < 8; r++) o[r] = o[r] * scale + w * (vf[r] + ef[r]);
        m = mn;
        e_cur = e_nxt; s_cur = s_nxt;
    }
    float invden = (deg > 0) ? (1.f / den) : 0.f;
    const __half* sp = g_qkvs + (size_t)bn*QKVS_W + 3*HD + h*DD + 8*lane;
    float sk[8];
    unpack8(*(const uint4*)sp, sk);
    __half2 hv[4];
#pragma unroll
    for (int r = 0; r < 4; r++) {
        float f0 = fmaxf(sk[2*r]   + o[2*r]   * invden, 0.f);
        float f1 = fmaxf(sk[2*r+1] + o[2*r+1] * invden, 0.f);
        hv[r] = __floats2half2_rn(f0, f1);
    }
    *(uint4*)(g_h + (size_t)bn*HD + h*DD + 8*lane) = *reinterpret_cast<uint4*>(hv);
}

// ================= inv path =================
__global__ void mixed_inv_k(const int* __restrict__ tok, const int* __restrict__ nod,
                            const float* __restrict__ emb) {
    int row = blockIdx.x, t = threadIdx.x;   // 128 threads
    int b = row / LL;
    int tk = tok[row], nd = nod[row];
    float2 f0 = *(const float2*)(emb + (size_t)tk*DD + 2*t);
    float2 f1 = __half22float2(*(const __half2*)(g_gr + (size_t)(b*NN + nd)*DD + 2*t));
    __half2 hv = __floats2half2_rn(f0.x + f1.x, f0.y + f1.y);
    *(uint32_t*)(g_inve + (size_t)row*DD + 2*t) = *reinterpret_cast<uint32_t*>(&hv);
}

// GRU: one block per batch, 384 threads, 2 gates/thread, W_hh fp16 packed
__global__ void gru_k(const float* __restrict__ b_hh) {
    __shared__ float hs[256];
    __shared__ float ghs[768];
    int b = blockIdx.x, t = threadIdx.x;  // 384 threads
    if (t < 256) hs[t] = 0.f;
    float bh0 = b_hh[t], bh1 = b_hh[t + 384];
    const uint4* W = (const uint4*)g_Wh8;
    __syncthreads();
    for (int l = 0; l < LL; l++) {
        float acc0 = bh0, acc1 = bh1;
#pragma unroll 8
        for (int j8 = 0; j8 < 32; j8++) {
            uint4 w0 = W[j8 * G3 + t];
            uint4 w1 = W[j8 * G3 + t + 384];
            float4 h0 = *(const float4*)(hs + 8*j8);
            float4 h1 = *(const float4*)(hs + 8*j8 + 4);
            float2 p;
            p = __half22float2(*reinterpret_cast<__half2*>(&w0.x));
            acc0 += h0.x*p.x + h0.y*p.y;
            p = __half22float2(*reinterpret_cast<__half2*>(&w0.y));
            acc0 += h0.z*p.x + h0.w*p.y;
            p = __half22float2(*reinterpret_cast<__half2*>(&w0.z));
            acc0 += h1.x*p.x + h1.y*p.y;
            p = __half22float2(*reinterpret_cast<__half2*>(&w0.w));
            acc0 += h1.z*p.x + h1.w*p.y;
            p = __half22float2(*reinterpret_cast<__half2*>(&w1.x));
            acc1 += h0.x*p.x + h0.y*p.y;
            p = __half22float2(*reinterpret_cast<__half2*>(&w1.y));
            acc1 += h0.z*p.x + h0.w*p.y;
            p = __half22float2(*reinterpret_cast<__half2*>(&w1.z));
            acc1 += h1.x*p.x + h1.y*p.y;
            p = __half22float2(*reinterpret_cast<__half2*>(&w1.w));
            acc1 += h1.z*p.x + h1.w*p.y;
        }
        ghs[t] = acc0;
        ghs[t + 384] = acc1;
        __syncthreads();
        float hn = 0.f;
        if (t < 256) {
            const float* g = g_gx + (size_t)(b*LL + l)*G3;
            float r = 1.f / (1.f + expf(-(g[t]       + ghs[t])));
            float z = 1.f / (1.f + expf(-(g[256 + t] + ghs[256 + t])));
            float c = tanhf(g[512 + t] + r * ghs[512 + t]);
            hn = (1.f - z) * c + z * hs[t];
        }
        __syncthreads();
        if (t < 256) hs[t] = hn;
        __syncthreads();
    }
    if (t < 256) g_invvec[b*OO + t] = hs[t];
}

// ================= scoring =================
__global__ void score_k(const float* __restrict__ Wap, const float* __restrict__ bap,
                        const float* __restrict__ Wab, const float* __restrict__ bab,
                        const int* __restrict__ aa_token, const int* __restrict__ aa_node,
                        const float* __restrict__ mask, const float* __restrict__ emb,
                        float* __restrict__ out) {
    __shared__ float invs[256];
    __shared__ float u[256];
    __shared__ float red[256];
    int b = blockIdx.x, t = threadIdx.x;
    int warp = t >> 5, lane = t & 31;
    invs[t] = g_invvec[b*OO + t];
    __syncthreads();
    for (int d = warp*32; d < warp*32 + 32; d++) {
        float acc = 0.f;
#pragma unroll
        for (int r = 0; r < 8; r++) {
            int o = lane + 32*r;
            acc += Wap[(size_t)d*OO + o] * invs[o];
        }
#pragma unroll
        for (int dd = 16; dd; dd >>= 1) acc += __shfl_xor_sync(0xffffffffu, acc, dd);
        if (lane == 0) u[d] = acc + Wab[d];
    }
    red[t] = bap[t] * invs[t];
    __syncthreads();
    for (int s = 128; s; s >>= 1) {
        if (t < s) red[t] += red[t + s];
        __syncthreads();
    }
    float cb = red[0] + bab[0];
    for (int a = warp; a < ACT; a += 8) {
        int tok = aa_token[b*ACT + a], nod = aa_node[b*ACT + a];
        const float* er = emb + (size_t)tok*DD;
        const __half* gg = g_gr + (size_t)(b*NN + nod)*DD;
        float acc = 0.f;
#pragma unroll
        for (int r = 0; r < 8; r++) {
            int d = lane + 32*r;
            acc += (er[d] + __half2float(gg[d])) * u[d];
        }
#pragma unroll
        for (int dd = 16; dd; dd >>= 1) acc += __shfl_xor_sync(0xffffffffu, acc, dd);
        if (lane == 0) {
            float mk = mask[b*ACT + a];
            float lm = fmaxf(logf(mk), -FLT_MAX);
            out[b*ACT + a] = acc + cb + lm;
        }
    }
}

// ================= host launcher =================
extern "C" void kernel_launch(void* const* d_in, const int* in_sizes, int n_in,
                              void* d_out, int out_size) {
    const int*   node_tokens = (const int*)d_in[0];
    const int*   edge_tokens = (const int*)d_in[1];
    const int*   edge_index  = (const int*)d_in[2];
    const int*   inv_token   = (const int*)d_in[3];
    const int*   inv_node    = (const int*)d_in[4];
    const int*   aa_token    = (const int*)d_in[5];
    const int*   aa_node     = (const int*)d_in[6];
    const float* action_mask = (const float*)d_in[7];
    const float* emb         = (const float*)d_in[8];
    const float* Wq  = (const float*)d_in[9];
    const float* bq  = (const float*)d_in[10];
    const float* Wk  = (const float*)d_in[11];
    const float* bk  = (const float*)d_in[12];
    const float* Wv  = (const float*)d_in[13];
    const float* bv  = (const float*)d_in[14];
    const float* We  = (const float*)d_in[15];
    const float* Wsk = (const float*)d_in[16];
    const float* bsk = (const float*)d_in[17];
    const float* W1  = (const float*)d_in[18];
    const float* b1  = (const float*)d_in[19];
    const float* Wp  = (const float*)d_in[20];
    const float* bp  = (const float*)d_in[21];
    const float* W_ih = (const float*)d_in[22];
    const float* W_hh = (const float*)d_in[23];
    const float* b_ih = (const float*)d_in[24];
    const float* b_hh = (const float*)d_in[25];
    const float* Wab = (const float*)d_in[26];
    const float* bab = (const float*)d_in[27];
    const float* Wap = (const float*)d_in[28];
    const float* bap = (const float*)d_in[29];
    float* out = (float*)d_out;

    void* p;
    __half *h_, *gr_, *inve_, *invh_, *bw1, *bwp, *bih;
    float *gx_;
    cudaGetSymbolAddress(&p, g_h);     h_ = (__half*)p;
    cudaGetSymbolAddress(&p, g_gr);    gr_ = (__half*)p;
    cudaGetSymbolAddress(&p, g_inve);  inve_ = (__half*)p;
    cudaGetSymbolAddress(&p, g_invh);  invh_ = (__half*)p;
    cudaGetSymbolAddress(&p, g_gx);    gx_ = (float*)p;
    cudaGetSymbolAddress(&p, g_bw1);   bw1 = (__half*)p;
    cudaGetSymbolAddress(&p, g_bwp);   bwp = (__half*)p;
    cudaGetSymbolAddress(&p, g_bih);   bih = (__half*)p;

    cudaFuncSetAttribute(gemm_big_k,      cudaFuncAttributeMaxDynamicSharedMemorySize, GEMM_SMEM);
    cudaFuncSetAttribute(mmagemm_k<1,0>,  cudaFuncAttributeMaxDynamicSharedMemorySize, GEMM_SMEM);
    cudaFuncSetAttribute(mmagemm_k<1,1>,  cudaFuncAttributeMaxDynamicSharedMemorySize, GEMM_SMEM);
    cudaFuncSetAttribute(mmagemm_k<0,0>,  cudaFuncAttributeMaxDynamicSharedMemorySize, GEMM_SMEM);

    // 1: all gathers + weight conversions + cnt zero, one launch
    prep_k<<<PREP_BLOCKS, 256>>>(node_tokens, edge_tokens, emb,
                                 Wq, Wk, Wv, Wsk, We, W1, Wp, W_ih, W_hh,
                                 bq, bk, bv, bsk);
    // 2-4: CSR
    count_k<<<(BB*EE + 255)/256, 256>>>(edge_index);
    scan_k<<<BB, 1024>>>();
    fill_k<<<(BB*EE + 255)/256, 256>>>(edge_index);
    // 5: combined edge + qkvs GEMM
    gemm_big_k<<<8000, 256, GEMM_SMEM>>>();
    // 6: fused attention + skip + relu -> fp16 h
    attn_fused_k<<<(BB*NN*NH + 3)/4, 128>>>(edge_index);
    // 7: graph_repr = relu(h@W1 + b1) -> fp16
    dim3 ggr(DD/128, (BB*NN)/128);
    mmagemm_k<1,1><<<ggr, 256, GEMM_SMEM>>>(h_, bw1, b1, nullptr, gr_, DD, HD);
    // 8-11: inv path
    mixed_inv_k<<<BB*LL, 128>>>(inv_token, inv_node, emb);
    dim3 ginv(DD/128, (BB*LL)/128);
    mmagemm_k<1,1><<<ginv, 256, GEMM_SMEM>>>(inve_, bwp, bp, nullptr, invh_, DD, DD);
    dim3 ggx(G3/128, (BB*LL)/128);
    mmagemm_k<0,0><<<ggx, 256, GEMM_SMEM>>>(invh_, bih, b_ih, gx_, nullptr, G3, DD);
    gru_k<<<BB, 384>>>(b_hh);
    // 12: scores
    score_k<<<BB, 256>>>(Wap, bap, Wab, bab, aa_token, aa_node, action_mask, emb, out);
    (void)in_sizes; (void)n_in; (void)out_size;
}

// round 17
// speedup vs baseline: 1.0622x; 1.0148x over previous
#include <cuda_runtime.h>
#include <cuda_fp16.h>
#include <math.h>
#include <float.h>
#include <stdint.h>

// Problem constants
#define BB 16
#define NN 1000
#define EE 4000
#define DD 256
#define NH 4
#define HD 1024
#define LL 64
#define ACT 128
#define OO 256
#define G3 768
#define QKVS_W 4096

// ================= scratch (device globals) =================
__device__ __align__(16) __half g_x[BB*NN*DD];
__device__ __align__(16) __half g_ea[BB*EE*DD];
__device__ __align__(16) __half g_qkvs[(size_t)BB*NN*QKVS_W];  // q|k|v|skip fp16
__device__ __align__(16) __half g_e[(size_t)BB*EE*HD];
__device__ __align__(16) __half g_h[(size_t)BB*NN*HD];
__device__ __align__(16) __half g_gr[BB*NN*DD];                // fp16 graph_repr
__device__ int   g_cnt[BB*NN];
__device__ int   g_off[BB*NN];
__device__ int   g_eord[BB*EE];
__device__ __align__(16) __half g_inve[BB*LL*DD];
__device__ __align__(16) __half g_invh[BB*LL*DD];
__device__ __align__(16) float g_gx[BB*LL*G3];
__device__ __align__(16) __half g_Wh8[DD*G3];   // W_hh fp16 packed (j8, g, 8)
__device__ float g_biasN[QKVS_W];
// fp16 weight buffers, [N,K] layout (k contiguous)
__device__ __align__(16) __half g_bN[QKVS_W*DD];
__device__ __align__(16) __half g_bE[HD*DD];
__device__ __align__(16) __half g_bw1[DD*HD];
__device__ __align__(16) __half g_bwp[DD*DD];
__device__ __align__(16) __half g_bih[G3*DD];

// ================= helpers =================
__device__ __forceinline__ uint32_t smem_to_u32(const void* smem_ptr) {
    uint32_t addr;
    asm("{ .reg .u64 tmp; cvta.to.shared.u64 tmp, %1; cvt.u32.u64 %0, tmp; }"
        : "=r"(addr) : "l"(smem_ptr));
    return addr;
}
__device__ __forceinline__ void ldsm4(uint32_t r[4], uint32_t addr) {
    asm volatile("ldmatrix.sync.aligned.m8n8.x4.shared.b16 {%0,%1,%2,%3}, [%4];"
        : "=r"(r[0]), "=r"(r[1]), "=r"(r[2]), "=r"(r[3]) : "r"(addr));
}
__device__ __forceinline__ void mma16816h(float c[4], uint32_t a0, uint32_t a1,
                                          uint32_t a2, uint32_t a3,
                                          uint32_t b0, uint32_t b1) {
    asm volatile(
        "mma.sync.aligned.m16n8k16.row.col.f32.f16.f16.f32 "
        "{%0,%1,%2,%3}, {%4,%5,%6,%7}, {%8,%9}, {%0,%1,%2,%3};"
        : "+f"(c[0]), "+f"(c[1]), "+f"(c[2]), "+f"(c[3])
        : "r"(a0), "r"(a1), "r"(a2), "r"(a3), "r"(b0), "r"(b1));
}
__device__ __forceinline__ void cpasync16(uint32_t dst, const void* src) {
    asm volatile("cp.async.cg.shared.global [%0], [%1], 16;" :: "r"(dst), "l"(src));
}
__device__ __forceinline__ void cp_commit() {
    asm volatile("cp.async.commit_group;");
}
template<int N> __device__ __forceinline__ void cp_wait() {
    asm volatile("cp.async.wait_group %0;" :: "n"(N));
}
__device__ __forceinline__ void unpack8(const uint4& w, float* f) {
    float2 p;
    p = __half22float2(*reinterpret_cast<const __half2*>(&w.x)); f[0]=p.x; f[1]=p.y;
    p = __half22float2(*reinterpret_cast<const __half2*>(&w.y)); f[2]=p.x; f[3]=p.y;
    p = __half22float2(*reinterpret_cast<const __half2*>(&w.z)); f[4]=p.x; f[5]=p.y;
    p = __half22float2(*reinterpret_cast<const __half2*>(&w.w)); f[6]=p.x; f[7]=p.y;
}

// ================= mega prep kernel (role by blockIdx range) =================
#define PB_GX   4000
#define PB_GEA  16000
#define PB_CVT  256
#define PB_W1   256
#define PB_WP   64
#define PB_IH   768
#define PB_WHH  96
#define PB_BIAS 16

__device__ __forceinline__ void convT_body(const float* __restrict__ W,
                                           __half* __restrict__ bh,
                                           int K, int N, int k0, int n0, int t) {
    __shared__ float tile[32][33];
    int tx = t & 31, ty = t >> 5;
#pragma unroll
    for (int j = 0; j < 4; j++)
        tile[ty + 8*j][tx] = W[(size_t)(k0 + ty + 8*j) * N + n0 + tx];
    __syncthreads();
#pragma unroll
    for (int j = 0; j < 4; j++)
        bh[(size_t)(n0 + ty + 8*j) * K + k0 + tx] = __float2half_rn(tile[tx][ty + 8*j]);
}
__device__ __forceinline__ void gather_body(__half* __restrict__ dst,
                                            const float* __restrict__ emb,
                                            const int* __restrict__ idx,
                                            int row, int lt) {
    int tok = idx[row];
    float4 f = *(const float4*)(emb + (size_t)tok*DD + 4*lt);
    __half2 p0 = __floats2half2_rn(f.x, f.y);
    __half2 p1 = __floats2half2_rn(f.z, f.w);
    uint2 o;
    o.x = *reinterpret_cast<uint32_t*>(&p0);
    o.y = *reinterpret_cast<uint32_t*>(&p1);
    *(uint2*)(dst + (size_t)row*DD + 4*lt) = o;
}

__global__ void prep_k(const int* __restrict__ node_tokens, const int* __restrict__ edge_tokens,
                       const float* __restrict__ emb,
                       const float* __restrict__ Wq, const float* __restrict__ Wk,
                       const float* __restrict__ Wv, const float* __restrict__ Wsk,
                       const float* __restrict__ We, const float* __restrict__ W1,
                       const float* __restrict__ Wp, const float* __restrict__ W_ih,
                       const float* __restrict__ W_hh,
                       const float* __restrict__ bq, const float* __restrict__ bk,
                       const float* __restrict__ bv, const float* __restrict__ bsk) {
    int bid = blockIdx.x, t = threadIdx.x;
    if (bid < PB_GX) {                                    // gather node emb
        gather_body(g_x, emb, node_tokens, bid*4 + (t >> 6), t & 63);
        return;
    }
    bid -= PB_GX;
    if (bid < PB_GEA) {                                   // gather edge emb
        gather_body(g_ea, emb, edge_tokens, bid*4 + (t >> 6), t & 63);
        return;
    }
    bid -= PB_GEA;
    if (bid < 5*PB_CVT) {                                 // Wq/Wk/Wv/Wsk/We [256,1024]
        int w = bid / PB_CVT, r = bid % PB_CVT;
        const float* W = (w==0) ? Wq : (w==1) ? Wk : (w==2) ? Wv : (w==3) ? Wsk : We;
        __half* dst = (w==4) ? g_bE : (g_bN + (size_t)w*1024*DD);
        convT_body(W, dst, DD, HD, (r & 7)*32, (r >> 3)*32, t);
        return;
    }
    bid -= 5*PB_CVT;
    if (bid < PB_W1) {                                    // W1 [1024,256]
        convT_body(W1, g_bw1, HD, DD, (bid & 31)*32, (bid >> 5)*32, t);
        return;
    }
    bid -= PB_W1;
    if (bid < PB_WP) {                                    // Wp [256,256]
        convT_body(Wp, g_bwp, DD, DD, (bid & 7)*32, (bid >> 3)*32, t);
        return;
    }
    bid -= PB_WP;
    if (bid < PB_IH) {                                    // W_ih elementwise
        int i = bid*256 + t;
        g_bih[i] = __float2half_rn(W_ih[i]);
        return;
    }
    bid -= PB_IH;
    if (bid < PB_WHH) {                                   // pack W_hh (j8,g,8)
        int sub = t >> 5, j8 = t & 31;
        int g = bid*8 + sub;
        float4 a = *(const float4*)(W_hh + (size_t)g*DD + 8*j8);
        float4 b = *(const float4*)(W_hh + (size_t)g*DD + 8*j8 + 4);
        __half2 h0 = __floats2half2_rn(a.x, a.y);
        __half2 h1 = __floats2half2_rn(a.z, a.w);
        __half2 h2 = __floats2half2_rn(b.x, b.y);
        __half2 h3 = __floats2half2_rn(b.z, b.w);
        uint4 o;
        o.x = *reinterpret_cast<uint32_t*>(&h0);
        o.y = *reinterpret_cast<uint32_t*>(&h1);
        o.z = *reinterpret_cast<uint32_t*>(&h2);
        o.w = *reinterpret_cast<uint32_t*>(&h3);
        *(uint4*)(g_Wh8 + ((size_t)j8*G3 + g)*8) = o;
        return;
    }
    bid -= PB_WHH;
    {                                                     // bias concat
        int i = bid*256 + t;
        const float* src = (i < 1024) ? bq : (i < 2048) ? bk : (i < 3072) ? bv : bsk;
        g_biasN[i] = src[i & 1023];
    }
}
#define PREP_BLOCKS (PB_GX + PB_GEA + 5*PB_CVT + PB_W1 + PB_WP + PB_IH + PB_WHH + PB_BIAS)

// ================= fused CSR: count + scan + fill in ONE kernel =================
__global__ __launch_bounds__(1024) void csr_k(const int* __restrict__ ei) {
    __shared__ int scnt[1024];
    __shared__ int scur[1024];
    int b = blockIdx.x, t = threadIdx.x;
    scnt[t] = 0;
    __syncthreads();
    const int* dstRow = ei + (b*2 + 1)*EE;
    for (int e = t; e < EE; e += 1024)
        atomicAdd(&scnt[dstRow[e]], 1);
    __syncthreads();
    int v = scnt[t];
    if (t < NN) g_cnt[b*NN + t] = v;
    for (int d = 1; d < 1024; d <<= 1) {
        int x = (t >= d) ? scnt[t - d] : 0;
        __syncthreads();
        scnt[t] += x;
        __syncthreads();
    }
    int excl = scnt[t] - v;
    if (t < NN) g_off[b*NN + t] = excl;
    scur[t] = excl;
    __syncthreads();
    for (int e = t; e < EE; e += 1024) {
        int pos = atomicAdd(&scur[dstRow[e]], 1);
        g_eord[b*EE + pos] = e;
    }
}

// ================= single-pass fp16 mma GEMM core =================
#define KC 32
#define RSB 80
#define STG_A 0
#define STG_B 10240
#define STAGE_SZ 20480
#define NSTAGE 3
#define GEMM_SMEM (NSTAGE*STAGE_SZ)

template<int CRELU, int OUTMODE>
__device__ __forceinline__ void gemm_core(
    char* smc, const __half* __restrict__ A, const __half* __restrict__ Bw,
    const float* __restrict__ bias, float* __restrict__ C,
    __half* __restrict__ Ch, int Nld, int K, int bm, int bn) {
    const uint32_t smb = smem_to_u32(smc);
    const int t = threadIdx.x, lane = t & 31, warp = t >> 5;
    const int wm = (warp >> 2) * 64, wn = (warp & 3) * 32;

    const int fr = t >> 1, fk = (t & 1) * 16;
    const __half* Ap = A  + (size_t)(bm + fr) * K + fk;
    const __half* Bp = Bw + (size_t)(bn + fr) * K + fk;
    const uint32_t fillOff = smb + (uint32_t)(fr * RSB + fk * 2);

    const uint32_t aBase = smb + (uint32_t)(wm + (lane & 15)) * RSB + (uint32_t)(lane >> 4) * 16;
    const uint32_t bBase = smb + (uint32_t)(wn + ((lane >> 4) << 3) + (lane & 7)) * RSB
                               + (uint32_t)((lane >> 3) & 1) * 16;

    float acc[4][4][4];
#pragma unroll
    for (int i = 0; i < 4; i++)
#pragma unroll
        for (int j = 0; j < 4; j++)
#pragma unroll
            for (int k = 0; k < 4; k++) acc[i][j][k] = 0.f;

    const int NC = K / KC;
#pragma unroll
    for (int c = 0; c < NSTAGE - 1; c++) {
        uint32_t d = fillOff + (uint32_t)(c * STAGE_SZ);
        const __half* a0 = Ap + c * KC;
        const __half* b0 = Bp + c * KC;
        cpasync16(d + STG_A,      a0);
        cpasync16(d + STG_A + 16, a0 + 8);
        cpasync16(d + STG_B,      b0);
        cpasync16(d + STG_B + 16, b0 + 8);
        cp_commit();
    }

    int stg_i = 0;                 // stage holding chunk c (== c mod NSTAGE)
    int fill_i = NSTAGE - 1;       // stage for chunk nx = c + NSTAGE-1 (== nx mod NSTAGE)
    for (int c = 0; c < NC; c++) {
        cp_wait<NSTAGE - 2>();
        __syncthreads();
        const uint32_t stg = (uint32_t)(stg_i * STAGE_SZ);
#pragma unroll
        for (int ks = 0; ks < 2; ks++) {
            const uint32_t kb = (uint32_t)(ks * 32);
            uint32_t br[2][4];
#pragma unroll
            for (int nb = 0; nb < 2; nb++)
                ldsm4(br[nb], bBase + stg + STG_B + (uint32_t)(nb * 16 * RSB) + kb);
            uint32_t ar[4][4];
#pragma unroll
            for (int mi = 0; mi < 4; mi++)
                ldsm4(ar[mi], aBase + stg + STG_A + (uint32_t)(mi * 16 * RSB) + kb);
#pragma unroll
            for (int mi = 0; mi < 4; mi++)
#pragma unroll
                for (int ni = 0; ni < 4; ni++)
                    mma16816h(acc[mi][ni], ar[mi][0], ar[mi][1], ar[mi][2], ar[mi][3],
                              br[ni>>1][(ni&1)*2], br[ni>>1][(ni&1)*2+1]);
        }
        __syncthreads();
        const int nx = c + NSTAGE - 1;
        if (nx < NC) {
            uint32_t d = fillOff + (uint32_t)(fill_i * STAGE_SZ);
            const __half* a0 = Ap + nx * KC;
            const __half* b0 = Bp + nx * KC;
            cpasync16(d + STG_A,      a0);
            cpasync16(d + STG_A + 16, a0 + 8);
            cpasync16(d + STG_B,      b0);
            cpasync16(d + STG_B + 16, b0 + 8);
        }
        cp_commit();
        stg_i  = (stg_i  + 1 == NSTAGE) ? 0 : stg_i  + 1;
        fill_i = (fill_i + 1 == NSTAGE) ? 0 : fill_i + 1;
    }

#pragma unroll
    for (int mi = 0; mi < 4; mi++) {
        const int r0 = bm + wm + mi*16 + (lane >> 2);
#pragma unroll
        for (int ni = 0; ni < 4; ni++) {
            const int col = bn + wn + ni*8 + (lane & 3)*2;
            float bx = 0.f, by = 0.f;
            if (bias) { bx = bias[col]; by = bias[col+1]; }
            float v0 = acc[mi][ni][0] + bx, v1 = acc[mi][ni][1] + by;
            float v2 = acc[mi][ni][2] + bx, v3 = acc[mi][ni][3] + by;
            if (CRELU) {
                v0 = fmaxf(v0, 0.f); v1 = fmaxf(v1, 0.f);
                v2 = fmaxf(v2, 0.f); v3 = fmaxf(v3, 0.f);
            }
            if (OUTMODE == 0) {
                *(float2*)(C + (size_t)r0 * Nld + col) = make_float2(v0, v1);
                *(float2*)(C + (size_t)(r0+8) * Nld + col) = make_float2(v2, v3);
            } else {
                __half2 p0 = __floats2half2_rn(v0, v1);
                __half2 p1 = __floats2half2_rn(v2, v3);
                *(uint32_t*)(Ch + (size_t)r0 * Nld + col) = *reinterpret_cast<uint32_t*>(&p0);
                *(uint32_t*)(Ch + (size_t)(r0+8) * Nld + col) = *reinterpret_cast<uint32_t*>(&p1);
            }
        }
    }
}

template<int CRELU, int OUTMODE>
__global__ __launch_bounds__(256, 1) void mmagemm_k(
    const __half* __restrict__ A, const __half* __restrict__ Bw,
    const float* __restrict__ bias, float* __restrict__ C,
    __half* __restrict__ Ch, int Nld, int K) {
    extern __shared__ char smc[];
    gemm_core<CRELU, OUTMODE>(smc, A, Bw, bias, C, Ch, Nld, K,
                              blockIdx.y * 128, blockIdx.x * 128);
}

// combined edge + qkvs GEMM (both fp16 out, K=256)
__global__ __launch_bounds__(256, 1) void gemm_big_k() {
    extern __shared__ char smc[];
    int cta = blockIdx.x;
    if (cta < 4000) {
        gemm_core<0, 1>(smc, g_ea, g_bE, nullptr, nullptr, g_e,
                        HD, DD, (cta >> 3) * 128, (cta & 7) * 128);
    } else {
        int r = cta - 4000;
        gemm_core<0, 1>(smc, g_x, g_bN, g_biasN, nullptr, g_qkvs,
                        QKVS_W, DD, (r >> 5) * 128, (r & 31) * 128);
    }
}

// ================= fused attention: uint4 loads + index prefetch =================
__global__ void attn_fused_k(const int* __restrict__ ei) {
    int g = blockIdx.x * 4 + (threadIdx.x >> 5);
    int lane = threadIdx.x & 31;
    if (g >= BB*NN*NH) return;
    int h = g & 3, bn = g >> 2;
    int b = bn / NN;
    int deg = g_cnt[bn], off = g_off[bn];
    const int off_b = b*EE + off;
    const int* srcRow = ei + (b*2)*EE;

    const __half* qp = g_qkvs + (size_t)bn*QKVS_W + h*DD + 8*lane;
    float q[8];
    unpack8(*(const uint4*)qp, q);

    float m = -3.0e38f, den = 0.f;
    float o[8];
#pragma unroll
    for (int r = 0; r < 8; r++) o[r] = 0.f;

    int e_cur = 0, s_cur = 0;
    if (deg > 0) { e_cur = g_eord[off_b]; s_cur = srcRow[e_cur]; }
    for (int i = 0; i < deg; i++) {
        int e_nxt = 0, s_nxt = 0;
        if (i + 1 < deg) { e_nxt = g_eord[off_b + i + 1]; s_nxt = srcRow[e_nxt]; }
        const __half* base = g_qkvs + (size_t)(b*NN + s_cur)*QKVS_W + h*DD + 8*lane;
        uint4 kw = *(const uint4*)(base + HD);
        uint4 vw = *(const uint4*)(base + 2*HD);
        uint4 ew = *(const uint4*)(g_e + (size_t)(b*EE + e_cur)*HD + h*DD + 8*lane);
        float kf[8], vf[8], ef[8];
        unpack8(kw, kf); unpack8(vw, vf); unpack8(ew, ef);
        float a = 0.f;
#pragma unroll
        for (int r = 0; r < 8; r++) a += q[r] * (kf[r] + ef[r]);
#pragma unroll
        for (int dlt = 16; dlt; dlt >>= 1) a += __shfl_xor_sync(0xffffffffu, a, dlt);
        a *= 0.0625f;
        float mn = fmaxf(m, a);
        float scale = expf(m - mn);
        float w = expf(a - mn);
        den = den * scale + w;
#pragma unroll
        for (int r = 0; r < 8; r++) o[r] = o[r] * scale + w * (vf[r] + ef[r]);
        m = mn;
        e_cur = e_nxt; s_cur = s_nxt;
    }
    float invden = (deg > 0) ? (1.f / den) : 0.f;
    const __half* sp = g_qkvs + (size_t)bn*QKVS_W + 3*HD + h*DD + 8*lane;
    float sk[8];
    unpack8(*(const uint4*)sp, sk);
    __half2 hv[4];
#pragma unroll
    for (int r = 0; r < 4; r++) {
        float f0 = fmaxf(sk[2*r]   + o[2*r]   * invden, 0.f);
        float f1 = fmaxf(sk[2*r+1] + o[2*r+1] * invden, 0.f);
        hv[r] = __floats2half2_rn(f0, f1);
    }
    *(uint4*)(g_h + (size_t)bn*HD + h*DD + 8*lane) = *reinterpret_cast<uint4*>(hv);
}

// ================= inv path =================
__global__ void mixed_inv_k(const int* __restrict__ tok, const int* __restrict__ nod,
                            const float* __restrict__ emb) {
    int row = blockIdx.x, t = threadIdx.x;   // 128 threads
    int b = row / LL;
    int tk = tok[row], nd = nod[row];
    float2 f0 = *(const float2*)(emb + (size_t)tk*DD + 2*t);
    float2 f1 = __half22float2(*(const __half2*)(g_gr + (size_t)(b*NN + nd)*DD + 2*t));
    __half2 hv = __floats2half2_rn(f0.x + f1.x, f0.y + f1.y);
    *(uint32_t*)(g_inve + (size_t)row*DD + 2*t) = *reinterpret_cast<uint32_t*>(&hv);
}

// ============ GRU + scoring fused: one block per batch, 384 threads ============
__global__ __launch_bounds__(384) void gru_score_k(
    const float* __restrict__ b_hh,
    const float* __restrict__ Wap, const float* __restrict__ bap,
    const float* __restrict__ Wab, const float* __restrict__ bab,
    const int* __restrict__ aa_token, const int* __restrict__ aa_node,
    const float* __restrict__ mask, const float* __restrict__ emb,
    float* __restrict__ out) {
    __shared__ float hs[256];
    __shared__ float ghs[768];
    __shared__ float u[256];
    __shared__ float red[256];
    int b = blockIdx.x, t = threadIdx.x;  // 384 threads
    int warp = t >> 5, lane = t & 31;
    if (t < 256) hs[t] = 0.f;
    float bh0 = b_hh[t], bh1 = b_hh[t + 384];
    const uint4* W = (const uint4*)g_Wh8;
    __syncthreads();
    for (int l = 0; l < LL; l++) {
        float acc0 = bh0, acc1 = bh1;
#pragma unroll 8
        for (int j8 = 0; j8 < 32; j8++) {
            uint4 w0 = W[j8 * G3 + t];
            uint4 w1 = W[j8 * G3 + t + 384];
            float4 h0 = *(const float4*)(hs + 8*j8);
            float4 h1 = *(const float4*)(hs + 8*j8 + 4);
            float2 p;
            p = __half22float2(*reinterpret_cast<__half2*>(&w0.x));
            acc0 += h0.x*p.x + h0.y*p.y;
            p = __half22float2(*reinterpret_cast<__half2*>(&w0.y));
            acc0 += h0.z*p.x + h0.w*p.y;
            p = __half22float2(*reinterpret_cast<__half2*>(&w0.z));
            acc0 += h1.x*p.x + h1.y*p.y;
            p = __half22float2(*reinterpret_cast<__half2*>(&w0.w));
            acc0 += h1.z*p.x + h1.w*p.y;
            p = __half22float2(*reinterpret_cast<__half2*>(&w1.x));
            acc1 += h0.x*p.x + h0.y*p.y;
            p = __half22float2(*reinterpret_cast<__half2*>(&w1.y));
            acc1 += h0.z*p.x + h0.w*p.y;
            p = __half22float2(*reinterpret_cast<__half2*>(&w1.z));
            acc1 += h1.x*p.x + h1.y*p.y;
            p = __half22float2(*reinterpret_cast<__half2*>(&w1.w));
            acc1 += h1.z*p.x + h1.w*p.y;
        }
        ghs[t] = acc0;
        ghs[t + 384] = acc1;
        __syncthreads();
        float hn = 0.f;
        if (t < 256) {
            const float* g = g_gx + (size_t)(b*LL + l)*G3;
            float r = 1.f / (1.f + expf(-(g[t]       + ghs[t])));
            float z = 1.f / (1.f + expf(-(g[256 + t] + ghs[256 + t])));
            float c = tanhf(g[512 + t] + r * ghs[512 + t]);
            hn = (1.f - z) * c + z * hs[t];
        }
        __syncthreads();
        if (t < 256) hs[t] = hn;
        __syncthreads();
    }
    // ---- scoring (final hidden state lives in hs[]) ----
    if (warp < 8) {
        for (int d = warp*32; d < warp*32 + 32; d++) {
            float acc = 0.f;
#pragma unroll
            for (int r = 0; r < 8; r++) {
                int o = lane + 32*r;
                acc += Wap[(size_t)d*OO + o] * hs[o];
            }
#pragma unroll
            for (int dd = 16; dd; dd >>= 1) acc += __shfl_xor_sync(0xffffffffu, acc, dd);
            if (lane == 0) u[d] = acc + Wab[d];
        }
    }
    if (t < 256) red[t] = bap[t] * hs[t];
    __syncthreads();
    for (int s = 128; s; s >>= 1) {
        if (t < s) red[t] += red[t + s];
        __syncthreads();
    }
    float cb = red[0] + bab[0];
    for (int a = warp; a < ACT; a += 12) {
        int tok = aa_token[b*ACT + a], nod = aa_node[b*ACT + a];
        const float* er = emb + (size_t)tok*DD;
        const __half* gg = g_gr + (size_t)(b*NN + nod)*DD;
        float acc = 0.f;
#pragma unroll
        for (int r = 0; r < 8; r++) {
            int d = lane + 32*r;
            acc += (er[d] + __half2float(gg[d])) * u[d];
        }
#pragma unroll
        for (int dd = 16; dd; dd >>= 1) acc += __shfl_xor_sync(0xffffffffu, acc, dd);
        if (lane == 0) {
            float mk = mask[b*ACT + a];
            float lm = fmaxf(logf(mk), -FLT_MAX);
            out[b*ACT + a] = acc + cb + lm;
        }
    }
}

// ================= host launcher =================
extern "C" void kernel_launch(void* const* d_in, const int* in_sizes, int n_in,
                              void* d_out, int out_size) {
    const int*   node_tokens = (const int*)d_in[0];
    const int*   edge_tokens = (const int*)d_in[1];
    const int*   edge_index  = (const int*)d_in[2];
    const int*   inv_token   = (const int*)d_in[3];
    const int*   inv_node    = (const int*)d_in[4];
    const int*   aa_token    = (const int*)d_in[5];
    const int*   aa_node     = (const int*)d_in[6];
    const float* action_mask = (const float*)d_in[7];
    const float* emb         = (const float*)d_in[8];
    const float* Wq  = (const float*)d_in[9];
    const float* bq  = (const float*)d_in[10];
    const float* Wk  = (const float*)d_in[11];
    const float* bk  = (const float*)d_in[12];
    const float* Wv  = (const float*)d_in[13];
    const float* bv  = (const float*)d_in[14];
    const float* We  = (const float*)d_in[15];
    const float* Wsk = (const float*)d_in[16];
    const float* bsk = (const float*)d_in[17];
    const float* W1  = (const float*)d_in[18];
    const float* b1  = (const float*)d_in[19];
    const float* Wp  = (const float*)d_in[20];
    const float* bp  = (const float*)d_in[21];
    const float* W_ih = (const float*)d_in[22];
    const float* W_hh = (const float*)d_in[23];
    const float* b_ih = (const float*)d_in[24];
    const float* b_hh = (const float*)d_in[25];
    const float* Wab = (const float*)d_in[26];
    const float* bab = (const float*)d_in[27];
    const float* Wap = (const float*)d_in[28];
    const float* bap = (const float*)d_in[29];
    float* out = (float*)d_out;

    void* p;
    __half *h_, *gr_, *inve_, *invh_, *bw1, *bwp, *bih;
    float *gx_;
    cudaGetSymbolAddress(&p, g_h);     h_ = (__half*)p;
    cudaGetSymbolAddress(&p, g_gr);    gr_ = (__half*)p;
    cudaGetSymbolAddress(&p, g_inve);  inve_ = (__half*)p;
    cudaGetSymbolAddress(&p, g_invh);  invh_ = (__half*)p;
    cudaGetSymbolAddress(&p, g_gx);    gx_ = (float*)p;
    cudaGetSymbolAddress(&p, g_bw1);   bw1 = (__half*)p;
    cudaGetSymbolAddress(&p, g_bwp);   bwp = (__half*)p;
    cudaGetSymbolAddress(&p, g_bih);   bih = (__half*)p;

    cudaFuncSetAttribute(gemm_big_k,      cudaFuncAttributeMaxDynamicSharedMemorySize, GEMM_SMEM);
    cudaFuncSetAttribute(mmagemm_k<1,0>,  cudaFuncAttributeMaxDynamicSharedMemorySize, GEMM_SMEM);
    cudaFuncSetAttribute(mmagemm_k<1,1>,  cudaFuncAttributeMaxDynamicSharedMemorySize, GEMM_SMEM);
    cudaFuncSetAttribute(mmagemm_k<0,0>,  cudaFuncAttributeMaxDynamicSharedMemorySize, GEMM_SMEM);

    // 1: all gathers + weight conversions, one launch
    prep_k<<<PREP_BLOCKS, 256>>>(node_tokens, edge_tokens, emb,
                                 Wq, Wk, Wv, Wsk, We, W1, Wp, W_ih, W_hh,
                                 bq, bk, bv, bsk);
    // 2: fused CSR (count + scan + fill)
    csr_k<<<BB, 1024>>>(edge_index);
    // 3: combined edge + qkvs GEMM
    gemm_big_k<<<8000, 256, GEMM_SMEM>>>();
    // 4: fused attention + skip + relu -> fp16 h
    attn_fused_k<<<(BB*NN*NH + 3)/4, 128>>>(edge_index);
    // 5: graph_repr = relu(h@W1 + b1) -> fp16
    dim3 ggr(DD/128, (BB*NN)/128);
    mmagemm_k<1,1><<<ggr, 256, GEMM_SMEM>>>(h_, bw1, b1, nullptr, gr_, DD, HD);
    // 6-8: inv path
    mixed_inv_k<<<BB*LL, 128>>>(inv_token, inv_node, emb);
    dim3 ginv(DD/128, (BB*LL)/128);
    mmagemm_k<1,1><<<ginv, 256, GEMM_SMEM>>>(inve_, bwp, bp, nullptr, invh_, DD, DD);
    dim3 ggx(G3/128, (BB*LL)/128);
    mmagemm_k<0,0><<<ggx, 256, GEMM_SMEM>>>(invh_, bih, b_ih, gx_, nullptr, G3, DD);
    // 9: GRU + scoring fused
    gru_score_k<<<BB, 384>>>(b_hh, Wap, bap, Wab, bab, aa_token, aa_node,
                             action_mask, emb, out);
    (void)in_sizes; (void)n_in; (void)out_size;
}